// round 1
// baseline (speedup 1.0000x reference)
#include <cuda_runtime.h>
#include <cstdint>

#define B_   8
#define CIN  64
#define COUT 8
#define H1   128
#define W1   128
#define H2   256
#define W2   256
#define PLANE (H2*W2)   /* 65536 */
#define NUM_ 8

// ---------------- scratch (device globals; no allocation allowed) ----------
__device__ float g_up [(size_t)B_*CIN *PLANE];  // upsampled input
__device__ float g_c1 [(size_t)B_*CIN *PLANE];  // conv1+BN+ReLU
__device__ float g_xf [(size_t)B_*COUT*PLANE];  // conv2+BN, thresholded
__device__ float g_rs [(size_t)B_*COUT*PLANE];  // row sums
__device__ float g_ws [(size_t)B_*COUT*PLANE];  // 5x5 window sums
__device__ float g_rm [(size_t)B_*COUT*PLANE];  // row max of ws
__device__ float g_msk[(size_t)B_*COUT*PLANE];  // NMS-masked ws
__device__ int   g_topidx[B_*COUT*NUM_];

// ---------------- 1) bilinear 2x upsample, half-pixel centers --------------
__global__ void k_upsample(const float* __restrict__ x) {
    int gid = blockIdx.x * blockDim.x + threadIdx.x;
    int plane = gid >> 16;          // b*64 + ci
    int r     = gid & 65535;
    int oy = r >> 8, ox = r & 255;
    // src coord = o/2 - 0.25
    int y0 = (oy - 1) >> 1;
    int x0 = (ox - 1) >> 1;
    float wy = (oy & 1) ? 0.25f : 0.75f;
    float wx = (ox & 1) ? 0.25f : 0.75f;
    int y0c = max(y0, 0), y1c = min(y0 + 1, H1 - 1);
    int x0c = max(x0, 0), x1c = min(x0 + 1, W1 - 1);
    const float* xp = x + (size_t)plane * (H1 * W1);
    float a = xp[y0c * W1 + x0c];
    float b = xp[y0c * W1 + x1c];
    float c = xp[y1c * W1 + x0c];
    float d = xp[y1c * W1 + x1c];
    float top = a + wx * (b - a);
    float bot = c + wx * (d - c);
    g_up[(size_t)plane * PLANE + r] = top + wy * (bot - top);
}

// ---------------- 2) conv3x3(64->64) + bias + BN + ReLU ---------------------
// block (32,8)=256 threads; tile 64(w) x 8(h); each thread: 2 pixels x 64 co
__global__ __launch_bounds__(256) void k_conv1(
    const float* __restrict__ w1, const float* __restrict__ b1,
    const float* __restrict__ gamma1, const float* __restrict__ beta1,
    const float* __restrict__ mean1, const float* __restrict__ var1)
{
    __shared__ float s_in[10][66];
    __shared__ float s_w[9][64];
    __shared__ float s_scale[64], s_shift[64];

    const int tx = threadIdx.x, ty = threadIdx.y;
    const int tid = ty * 32 + tx;
    const int b  = blockIdx.z;
    const int y0 = blockIdx.y * 8;
    const int x0 = blockIdx.x * 64;

    if (tid < 64) {
        float a = gamma1[tid] * rsqrtf(var1[tid] + 1e-5f);
        s_scale[tid] = a;
        s_shift[tid] = a * (b1[tid] - mean1[tid]) + beta1[tid];
    }

    float acc[128];
#pragma unroll
    for (int i = 0; i < 128; i++) acc[i] = 0.f;

    for (int ci = 0; ci < CIN; ci++) {
        __syncthreads();
        const float* up = g_up + ((size_t)(b * CIN + ci)) * PLANE;
        for (int i = tid; i < 10 * 66; i += 256) {
            int r = i / 66, c = i % 66;
            int gy = y0 + r - 1, gx = x0 + c - 1;
            float v = 0.f;
            if (gy >= 0 && gy < H2 && gx >= 0 && gx < W2) v = up[gy * W2 + gx];
            s_in[r][c] = v;
        }
        for (int i = tid; i < 576; i += 256) {
            int co = i / 9, p = i % 9;
            s_w[p][co] = w1[(co * CIN + ci) * 9 + p];
        }
        __syncthreads();

        float v[3][4];
#pragma unroll
        for (int r = 0; r < 3; r++)
#pragma unroll
            for (int c = 0; c < 4; c++)
                v[r][c] = s_in[ty + r][2 * tx + c];

#pragma unroll
        for (int p = 0; p < 9; p++) {
            const int kr = p / 3, kc = p % 3;
            float i0 = v[kr][kc];
            float i1 = v[kr][kc + 1];
#pragma unroll
            for (int q = 0; q < 16; q++) {
                float4 wv = *(const float4*)&s_w[p][q * 4];
                acc[(q*4+0)*2+0] += i0 * wv.x; acc[(q*4+0)*2+1] += i1 * wv.x;
                acc[(q*4+1)*2+0] += i0 * wv.y; acc[(q*4+1)*2+1] += i1 * wv.y;
                acc[(q*4+2)*2+0] += i0 * wv.z; acc[(q*4+2)*2+1] += i1 * wv.z;
                acc[(q*4+3)*2+0] += i0 * wv.w; acc[(q*4+3)*2+1] += i1 * wv.w;
            }
        }
    }
    __syncthreads();

    const int ox = x0 + 2 * tx;
    const int oy = y0 + ty;
    float* outb = g_c1 + ((size_t)b * CIN) * PLANE + oy * W2 + ox;
#pragma unroll
    for (int co = 0; co < 64; co++) {
        float o0 = fmaxf(fmaf(s_scale[co], acc[co * 2 + 0], s_shift[co]), 0.f);
        float o1 = fmaxf(fmaf(s_scale[co], acc[co * 2 + 1], s_shift[co]), 0.f);
        *(float2*)(outb + (size_t)co * PLANE) = make_float2(o0, o1);
    }
}

// ---------------- 3) conv1x1(64->8) + BN + threshold (RF=1.0) ---------------
__global__ void k_conv2(const float* __restrict__ w2,
                        const float* __restrict__ gamma2, const float* __restrict__ beta2,
                        const float* __restrict__ mean2, const float* __restrict__ var2)
{
    __shared__ float s_w[512];
    __shared__ float s_scale[8], s_shift[8];
    int tid = threadIdx.x;
    int g = blockIdx.x * 256 + tid;
    if (tid < 8) {
        float a = gamma2[tid] * rsqrtf(var2[tid] + 1e-5f);
        s_scale[tid] = a;
        s_shift[tid] = beta2[tid] - a * mean2[tid];
    }
    for (int i = tid; i < 512; i += 256) s_w[i] = w2[i];
    __syncthreads();

    int b = g >> 16;
    int pix = g & 65535;
    const float* c1 = g_c1 + (size_t)b * CIN * PLANE + pix;
    float acc[8];
#pragma unroll
    for (int co = 0; co < 8; co++) acc[co] = 0.f;
    for (int ci = 0; ci < CIN; ci++) {
        float v = c1[(size_t)ci * PLANE];
#pragma unroll
        for (int co = 0; co < 8; co++) acc[co] += v * s_w[co * 64 + ci];
    }
#pragma unroll
    for (int co = 0; co < 8; co++) {
        float o = fmaf(s_scale[co], acc[co], s_shift[co]);
        g_xf[((size_t)b * COUT + co) * PLANE + pix] = (o > 1.0f) ? o : 0.f;
    }
}

// ---------------- 4) separable 5x5 window sum (zero pad) --------------------
__global__ void k_rowsum() {
    int gid = blockIdx.x * blockDim.x + threadIdx.x;
    int x = gid & 255;
    int base = gid - x;
    float s = 0.f;
#pragma unroll
    for (int d = -2; d <= 2; d++) {
        int xx = x + d;
        if (xx >= 0 && xx < 256) s += g_xf[base + xx];
    }
    g_rs[gid] = s;
}
__global__ void k_colsum() {
    int gid = blockIdx.x * blockDim.x + threadIdx.x;
    int x = gid & 255;
    int y = (gid >> 8) & 255;
    int pl = gid >> 16;
    float s = 0.f;
#pragma unroll
    for (int d = -2; d <= 2; d++) {
        int yy = y + d;
        if (yy >= 0 && yy < 256) s += g_rs[((size_t)pl << 16) + (yy << 8) + x];
    }
    g_ws[gid] = s;
}

// ---------------- 5) separable 5x5 max + NMS mask ---------------------------
__global__ void k_rowmax() {
    int gid = blockIdx.x * blockDim.x + threadIdx.x;
    int x = gid & 255;
    int base = gid - x;
    float m = -1.f; // ws >= 0 always, OOB padded with -inf in reference => skip
#pragma unroll
    for (int d = -2; d <= 2; d++) {
        int xx = x + d;
        if (xx >= 0 && xx < 256) m = fmaxf(m, g_ws[base + xx]);
    }
    g_rm[gid] = m;
}
__global__ void k_masked() {
    int gid = blockIdx.x * blockDim.x + threadIdx.x;
    int x = gid & 255;
    int y = (gid >> 8) & 255;
    int pl = gid >> 16;
    float m = -1.f;
#pragma unroll
    for (int d = -2; d <= 2; d++) {
        int yy = y + d;
        if (yy >= 0 && yy < 256) m = fmaxf(m, g_rm[((size_t)pl << 16) + (yy << 8) + x]);
    }
    float w = g_ws[gid];
    g_msk[gid] = (w == m) ? w : 0.f;
}

// ---------------- 6) top-8 per (b, co), ties -> lowest index ----------------
// key = (float_bits << 32) | ~index  (valid: masked >= 0 so bits are ordered)
__global__ void k_topk() {
    __shared__ unsigned long long s[256 * 8];
    const int bc = blockIdx.x;
    const int tid = threadIdx.x;
    const float* m = g_msk + (size_t)bc * PLANE;

    unsigned long long k[8];
#pragma unroll
    for (int j = 0; j < 8; j++) k[j] = 0ull;

    for (int it = 0; it < 256; it++) {
        int pos = tid + (it << 8);
        float v = m[pos];
        unsigned long long key =
            ((unsigned long long)__float_as_uint(v) << 32) | (unsigned)(~(unsigned)pos);
        if (key > k[7]) {
            int p = 7;
#pragma unroll
            for (int q = 7; q > 0; q--) {
                if (key > k[q - 1]) { k[q] = k[q - 1]; p = q - 1; }
            }
            k[p] = key;
        }
    }
#pragma unroll
    for (int j = 0; j < 8; j++) s[tid * 8 + j] = k[j];
    __syncthreads();

    for (int off = 128; off > 0; off >>= 1) {
        if (tid < off) {
            unsigned long long* a = &s[tid * 8];
            unsigned long long* b = &s[(tid + off) * 8];
            unsigned long long out[8];
            int i = 0, j = 0;
#pragma unroll
            for (int t = 0; t < 8; t++)
                out[t] = (a[i] >= b[j]) ? a[i++] : b[j++];
#pragma unroll
            for (int t = 0; t < 8; t++) a[t] = out[t];
        }
        __syncthreads();
    }
    if (tid < 8) {
        unsigned pos = ~(unsigned)(s[tid] & 0xFFFFFFFFull);
        g_topidx[bc * 8 + tid] = (int)pos;
    }
}

// ---------------- 7) gather 5x5 patches + positions -------------------------
// out layout: [0 .. 12800): patches (B,C,NUM,5,5); [12800 .. 14848): positions (B,C,NUM,4)
__global__ void k_gather(float* __restrict__ out) {
    int gid = blockIdx.x * blockDim.x + threadIdx.x;
    if (gid >= B_ * COUT * NUM_) return;
    int bc = gid >> 3;
    int pos = g_topidx[gid];
    int h = pos >> 8, w = pos & 255;
    const float* xf = g_xf + (size_t)bc * PLANE;
    float* po = out + gid * 25;
#pragma unroll
    for (int dy = 0; dy < 5; dy++) {
        int yy = h + dy - 2;
#pragma unroll
        for (int dx = 0; dx < 5; dx++) {
            int xx = w + dx - 2;
            float v = 0.f;
            if (yy >= 0 && yy < 256 && xx >= 0 && xx < 256) v = xf[yy * 256 + xx];
            po[dy * 5 + dx] = v;
        }
    }
    float* pp = out + B_ * COUT * NUM_ * 25 + gid * 4;
    pp[0] = (float)min(max(w - 2, 0), 255);  // x1
    pp[1] = (float)min(max(h - 2, 0), 255);  // y1
    pp[2] = (float)min(max(w + 2, 0), 255);  // x2
    pp[3] = (float)min(max(h + 2, 0), 255);  // y2
}

// ---------------- launch -----------------------------------------------------
extern "C" void kernel_launch(void* const* d_in, const int* in_sizes, int n_in,
                              void* d_out, int out_size) {
    const float* x      = (const float*)d_in[0];
    const float* w1     = (const float*)d_in[1];
    const float* b1     = (const float*)d_in[2];
    const float* gamma1 = (const float*)d_in[3];
    const float* beta1  = (const float*)d_in[4];
    const float* mean1  = (const float*)d_in[5];
    const float* var1   = (const float*)d_in[6];
    const float* w2     = (const float*)d_in[7];
    const float* gamma2 = (const float*)d_in[8];
    const float* beta2  = (const float*)d_in[9];
    const float* mean2  = (const float*)d_in[10];
    const float* var2   = (const float*)d_in[11];
    float* out = (float*)d_out;

    k_upsample<<<(B_ * CIN * PLANE) / 256, 256>>>(x);

    dim3 cb(32, 8);
    dim3 cg(W2 / 64, H2 / 8, B_);
    k_conv1<<<cg, cb>>>(w1, b1, gamma1, beta1, mean1, var1);

    k_conv2<<<(B_ * PLANE) / 256, 256>>>(w2, gamma2, beta2, mean2, var2);

    const int n = B_ * COUT * PLANE;
    k_rowsum<<<n / 256, 256>>>();
    k_colsum<<<n / 256, 256>>>();
    k_rowmax<<<n / 256, 256>>>();
    k_masked<<<n / 256, 256>>>();

    k_topk<<<B_ * COUT, 256>>>();
    k_gather<<<2, 256>>>(out);
}

// round 2
// speedup vs baseline: 1.1002x; 1.1002x over previous
#include <cuda_runtime.h>
#include <cstdint>

#define B_   8
#define CIN  64
#define COUT 8
#define H1   128
#define W1   128
#define H2   256
#define W2   256
#define PLANE (H2*W2)   /* 65536 */
#define NUM_ 8

// ---------------- scratch (device globals; no allocation allowed) ----------
__device__ float g_up [(size_t)B_*CIN *PLANE];  // upsampled input
__device__ float g_c1 [(size_t)B_*CIN *PLANE];  // conv1+BN+ReLU
__device__ float g_xf [(size_t)B_*COUT*PLANE];  // conv2+BN, thresholded
__device__ float g_rs [(size_t)B_*COUT*PLANE];  // row sums
__device__ float g_ws [(size_t)B_*COUT*PLANE];  // 5x5 window sums
__device__ float g_rm [(size_t)B_*COUT*PLANE];  // row max of ws
__device__ int   g_topidx[B_*COUT*NUM_];

// ---------------- packed f32x2 helpers --------------------------------------
__device__ __forceinline__ unsigned long long pk2(float lo, float hi) {
    unsigned long long r;
    asm("mov.b64 %0, {%1, %2};" : "=l"(r) : "f"(lo), "f"(hi));
    return r;
}
__device__ __forceinline__ void upk2(unsigned long long v, float& lo, float& hi) {
    asm("mov.b64 {%0, %1}, %2;" : "=f"(lo), "=f"(hi) : "l"(v));
}
#define FMA2(d, a, b) asm("fma.rn.f32x2 %0, %1, %2, %0;" : "+l"(d) : "l"(a), "l"(b))

// ---------------- 1) bilinear 2x upsample, half-pixel centers --------------
__global__ void k_upsample(const float* __restrict__ x) {
    int gid = blockIdx.x * blockDim.x + threadIdx.x;
    int plane = gid >> 16;          // b*64 + ci
    int r     = gid & 65535;
    int oy = r >> 8, ox = r & 255;
    int y0 = (oy - 1) >> 1;
    int x0 = (ox - 1) >> 1;
    float wy = (oy & 1) ? 0.25f : 0.75f;
    float wx = (ox & 1) ? 0.25f : 0.75f;
    int y0c = max(y0, 0), y1c = min(y0 + 1, H1 - 1);
    int x0c = max(x0, 0), x1c = min(x0 + 1, W1 - 1);
    const float* xp = x + (size_t)plane * (H1 * W1);
    float a = xp[y0c * W1 + x0c];
    float b = xp[y0c * W1 + x1c];
    float c = xp[y1c * W1 + x0c];
    float d = xp[y1c * W1 + x1c];
    float top = a + wx * (b - a);
    float bot = c + wx * (d - c);
    g_up[(size_t)plane * PLANE + r] = top + wy * (bot - top);
}

// ---------------- 2) conv3x3(64->64) + bias + BN + ReLU ---------------------
// block 256 threads; tile 64(w) x 8(h); grid.z = batch * 2 (co halves of 32)
// thread: 4 pixels (2 f32x2 pairs) x 16 co; packed FFMA2 inner loop.
__global__ __launch_bounds__(256) void k_conv1(
    const float* __restrict__ w1, const float* __restrict__ b1,
    const float* __restrict__ gamma1, const float* __restrict__ beta1,
    const float* __restrict__ mean1, const float* __restrict__ var1)
{
    __shared__ float  s_in[2][10][68];
    __shared__ float2 s_w[2][2][9][16];   // [buf][cg][tap][co] duplicated (w,w)
    __shared__ float  s_scale[64], s_shift[64];

    const int tid = threadIdx.x;
    const int xg = tid & 15;
    const int yg = (tid >> 4) & 7;
    const int cg = tid >> 7;              // 0 or 1 (16-co group within half)
    const int bz = blockIdx.z;
    const int b    = bz >> 1;
    const int half = bz & 1;              // which 32-co half
    const int x0t = blockIdx.x * 64;
    const int y0t = blockIdx.y * 8;

    if (tid < 64) {
        float a = gamma1[tid] * rsqrtf(var1[tid] + 1e-5f);
        s_scale[tid] = a;
        s_shift[tid] = fmaf(a, b1[tid] - mean1[tid], beta1[tid]);
    }

    unsigned long long accA[16], accB[16];
#pragma unroll
    for (int i = 0; i < 16; i++) { accA[i] = 0ull; accB[i] = 0ull; }

    const float* upb = g_up + (size_t)b * CIN * PLANE;
    const float* w1b = w1 + (size_t)(half * 32) * CIN * 9;

    // ---- fill smem for channel ci into buffer buf ----
#define FILL(ci, buf) do {                                                    \
        const float* up_ = upb + (size_t)(ci) * PLANE;                        \
        for (int i_ = tid; i_ < 680; i_ += 256) {                             \
            int r_ = i_ / 68, c_ = i_ - r_ * 68;                             \
            float v_ = 0.f;                                                   \
            int gy_ = y0t + r_ - 1, gx_ = x0t + c_ - 1;                       \
            if (c_ < 66 && gy_ >= 0 && gy_ < H2 && gx_ >= 0 && gx_ < W2)      \
                v_ = up_[(gy_ << 8) + gx_];                                   \
            s_in[buf][r_][c_] = v_;                                           \
        }                                                                     \
        for (int i_ = tid; i_ < 288; i_ += 256) {                             \
            int col_ = i_ / 9, p_ = i_ - col_ * 9;                            \
            float w_ = w1b[((size_t)col_ * CIN + (ci)) * 9 + p_];             \
            s_w[buf][col_ >> 4][p_][col_ & 15] = make_float2(w_, w_);         \
        }                                                                     \
    } while (0)

    FILL(0, 0);
    __syncthreads();

    for (int ci = 0; ci < CIN; ci++) {
        const int cur = ci & 1;
        if (ci < CIN - 1) FILL(ci + 1, cur ^ 1);

        // 3 input rows, 5 shifted pairs each
        unsigned long long P[3][5];
#pragma unroll
        for (int r = 0; r < 3; r++) {
            const float* row = &s_in[cur][yg + r][xg * 4];
            float4 F = *(const float4*)row;
            float2 G = *(const float2*)(row + 4);
            P[r][0] = pk2(F.x, F.y);
            P[r][1] = pk2(F.y, F.z);
            P[r][2] = pk2(F.z, F.w);
            P[r][3] = pk2(F.w, G.x);
            P[r][4] = pk2(G.x, G.y);
        }

#pragma unroll
        for (int p = 0; p < 9; p++) {
            const int kr = p / 3, kc = p % 3;
            unsigned long long iA = P[kr][kc];
            unsigned long long iB = P[kr][kc + 2];
            const ulonglong2* wrow = (const ulonglong2*)&s_w[cur][cg][p][0];
#pragma unroll
            for (int j = 0; j < 8; j++) {
                ulonglong2 w2 = wrow[j];
                FMA2(accA[2 * j],     iA, w2.x);
                FMA2(accB[2 * j],     iB, w2.x);
                FMA2(accA[2 * j + 1], iA, w2.y);
                FMA2(accB[2 * j + 1], iB, w2.y);
            }
        }
        __syncthreads();
    }
#undef FILL

    const int ox = x0t + xg * 4;
    const int oy = y0t + yg;
    const int co0 = half * 32 + cg * 16;
    float* outp = g_c1 + (((size_t)b * CIN + co0) << 16) + (oy << 8) + ox;
#pragma unroll
    for (int j = 0; j < 16; j++) {
        float a0, a1, c0, c1v;
        upk2(accA[j], a0, a1);
        upk2(accB[j], c0, c1v);
        const float sc = s_scale[co0 + j], sh = s_shift[co0 + j];
        float4 o;
        o.x = fmaxf(fmaf(sc, a0,  sh), 0.f);
        o.y = fmaxf(fmaf(sc, a1,  sh), 0.f);
        o.z = fmaxf(fmaf(sc, c0,  sh), 0.f);
        o.w = fmaxf(fmaf(sc, c1v, sh), 0.f);
        *(float4*)(outp + ((size_t)j << 16)) = o;
    }
}

// ---------------- 3) conv1x1(64->8) + BN + threshold (RF=1.0) ---------------
__global__ void k_conv2(const float* __restrict__ w2,
                        const float* __restrict__ gamma2, const float* __restrict__ beta2,
                        const float* __restrict__ mean2, const float* __restrict__ var2)
{
    __shared__ float s_w[512];
    __shared__ float s_scale[8], s_shift[8];
    int tid = threadIdx.x;
    int g = blockIdx.x * 256 + tid;
    if (tid < 8) {
        float a = gamma2[tid] * rsqrtf(var2[tid] + 1e-5f);
        s_scale[tid] = a;
        s_shift[tid] = beta2[tid] - a * mean2[tid];
    }
    for (int i = tid; i < 512; i += 256) s_w[i] = w2[i];
    __syncthreads();

    int b = g >> 16;
    int pix = g & 65535;
    const float* c1 = g_c1 + (size_t)b * CIN * PLANE + pix;
    float acc[8];
#pragma unroll
    for (int co = 0; co < 8; co++) acc[co] = 0.f;
    for (int ci = 0; ci < CIN; ci++) {
        float v = c1[(size_t)ci * PLANE];
#pragma unroll
        for (int co = 0; co < 8; co++) acc[co] += v * s_w[co * 64 + ci];
    }
#pragma unroll
    for (int co = 0; co < 8; co++) {
        float o = fmaf(s_scale[co], acc[co], s_shift[co]);
        g_xf[((size_t)b * COUT + co) * PLANE + pix] = (o > 1.0f) ? o : 0.f;
    }
}

// ---------------- 4) separable 5x5 window sum (zero pad) --------------------
__global__ void k_rowsum() {
    int gid = blockIdx.x * blockDim.x + threadIdx.x;
    int x = gid & 255;
    int base = gid - x;
    float s = 0.f;
#pragma unroll
    for (int d = -2; d <= 2; d++) {
        int xx = x + d;
        if (xx >= 0 && xx < 256) s += g_xf[base + xx];
    }
    g_rs[gid] = s;
}
__global__ void k_colsum() {
    int gid = blockIdx.x * blockDim.x + threadIdx.x;
    int x = gid & 255;
    int y = (gid >> 8) & 255;
    int pl = gid >> 16;
    float s = 0.f;
#pragma unroll
    for (int d = -2; d <= 2; d++) {
        int yy = y + d;
        if (yy >= 0 && yy < 256) s += g_rs[((size_t)pl << 16) + (yy << 8) + x];
    }
    g_ws[gid] = s;
}

// ---------------- 5) row max of ws -------------------------------------------
__global__ void k_rowmax() {
    int gid = blockIdx.x * blockDim.x + threadIdx.x;
    int x = gid & 255;
    int base = gid - x;
    float m = -1.f; // ws >= 0 always; OOB in reference is -inf => exclude
#pragma unroll
    for (int d = -2; d <= 2; d++) {
        int xx = x + d;
        if (xx >= 0 && xx < 256) m = fmaxf(m, g_ws[base + xx]);
    }
    g_rm[gid] = m;
}

// ---------------- 6) fused NMS mask + top-8 per (b, co) ---------------------
// key = (float_bits << 32) | ~index  -> ties break to lowest index (lax.top_k)
__global__ void k_topk() {
    __shared__ unsigned long long s[256 * 8];
    const int bc = blockIdx.x;
    const int x = threadIdx.x;            // one column per thread
    const float* ws = g_ws + (size_t)bc * PLANE;
    const float* rm = g_rm + (size_t)bc * PLANE;

    unsigned long long k[8];
#pragma unroll
    for (int j = 0; j < 8; j++) k[j] = 0ull;

    // rolling 5-row window of row-max for column max
    float w0 = -1.f, w1 = -1.f, w2 = rm[x], w3 = rm[256 + x], w4;
    for (int y = 0; y < 256; y++) {
        w4 = (y + 2 < 256) ? rm[((y + 2) << 8) + x] : -1.f;
        float m = fmaxf(fmaxf(fmaxf(w0, w1), fmaxf(w2, w3)), w4);
        float v = ws[(y << 8) + x];
        if (v == m) {
            unsigned pos = (unsigned)((y << 8) + x);
            unsigned long long key =
                ((unsigned long long)__float_as_uint(v) << 32) | (unsigned)(~pos);
            if (key > k[7]) {
                int p = 7;
#pragma unroll
                for (int q = 7; q > 0; q--) {
                    if (key > k[q - 1]) { k[q] = k[q - 1]; p = q - 1; }
                }
                k[p] = key;
            }
        }
        w0 = w1; w1 = w2; w2 = w3; w3 = w4;
    }
#pragma unroll
    for (int j = 0; j < 8; j++) s[x * 8 + j] = k[j];
    __syncthreads();

    for (int off = 128; off > 0; off >>= 1) {
        if (x < off) {
            unsigned long long* a = &s[x * 8];
            unsigned long long* b = &s[(x + off) * 8];
            unsigned long long out[8];
            int i = 0, j = 0;
#pragma unroll
            for (int t = 0; t < 8; t++)
                out[t] = (a[i] >= b[j]) ? a[i++] : b[j++];
#pragma unroll
            for (int t = 0; t < 8; t++) a[t] = out[t];
        }
        __syncthreads();
    }
    if (x < 8) {
        unsigned pos = ~(unsigned)(s[x] & 0xFFFFFFFFull);
        g_topidx[bc * 8 + x] = (int)pos;
    }
}

// ---------------- 7) gather 5x5 patches + positions -------------------------
__global__ void k_gather(float* __restrict__ out) {
    int gid = blockIdx.x * blockDim.x + threadIdx.x;
    if (gid >= B_ * COUT * NUM_) return;
    int bc = gid >> 3;
    int pos = g_topidx[gid];
    int h = pos >> 8, w = pos & 255;
    const float* xf = g_xf + (size_t)bc * PLANE;
    float* po = out + gid * 25;
#pragma unroll
    for (int dy = 0; dy < 5; dy++) {
        int yy = h + dy - 2;
#pragma unroll
        for (int dx = 0; dx < 5; dx++) {
            int xx = w + dx - 2;
            float v = 0.f;
            if (yy >= 0 && yy < 256 && xx >= 0 && xx < 256) v = xf[yy * 256 + xx];
            po[dy * 5 + dx] = v;
        }
    }
    float* pp = out + B_ * COUT * NUM_ * 25 + gid * 4;
    pp[0] = (float)min(max(w - 2, 0), 255);
    pp[1] = (float)min(max(h - 2, 0), 255);
    pp[2] = (float)min(max(w + 2, 0), 255);
    pp[3] = (float)min(max(h + 2, 0), 255);
}

// ---------------- launch -----------------------------------------------------
extern "C" void kernel_launch(void* const* d_in, const int* in_sizes, int n_in,
                              void* d_out, int out_size) {
    const float* x      = (const float*)d_in[0];
    const float* w1     = (const float*)d_in[1];
    const float* b1     = (const float*)d_in[2];
    const float* gamma1 = (const float*)d_in[3];
    const float* beta1  = (const float*)d_in[4];
    const float* mean1  = (const float*)d_in[5];
    const float* var1   = (const float*)d_in[6];
    const float* w2     = (const float*)d_in[7];
    const float* gamma2 = (const float*)d_in[8];
    const float* beta2  = (const float*)d_in[9];
    const float* mean2  = (const float*)d_in[10];
    const float* var2   = (const float*)d_in[11];
    float* out = (float*)d_out;

    k_upsample<<<(B_ * CIN * PLANE) / 256, 256>>>(x);

    dim3 cg(W2 / 64, H2 / 8, B_ * 2);
    k_conv1<<<cg, 256>>>(w1, b1, gamma1, beta1, mean1, var1);

    k_conv2<<<(B_ * PLANE) / 256, 256>>>(w2, gamma2, beta2, mean2, var2);

    const int n = B_ * COUT * PLANE;
    k_rowsum<<<n / 256, 256>>>();
    k_colsum<<<n / 256, 256>>>();
    k_rowmax<<<n / 256, 256>>>();

    k_topk<<<B_ * COUT, 256>>>();
    k_gather<<<2, 256>>>(out);
}

// round 3
// speedup vs baseline: 1.6344x; 1.4855x over previous
#include <cuda_runtime.h>
#include <cstdint>

#define B_   8
#define CIN  64
#define COUT 8
#define H1   128
#define W1   128
#define H2   256
#define W2   256
#define PLANE (H2*W2)   /* 65536 */
#define NUM_ 8

// ---------------- scratch (device globals; no allocation allowed) ----------
__device__ float g_c1 [(size_t)B_*CIN *PLANE];  // conv1+BN+ReLU
__device__ float g_xf [(size_t)B_*COUT*PLANE];  // conv2+BN, thresholded
__device__ float g_rs [(size_t)B_*COUT*PLANE];  // row sums
__device__ float g_ws [(size_t)B_*COUT*PLANE];  // 5x5 window sums
__device__ float g_rm [(size_t)B_*COUT*PLANE];  // row max of ws
__device__ int   g_topidx[B_*COUT*NUM_];

// ---------------- packed f32x2 helpers --------------------------------------
__device__ __forceinline__ unsigned long long pk2(float lo, float hi) {
    unsigned long long r;
    asm("mov.b64 %0, {%1, %2};" : "=l"(r) : "f"(lo), "f"(hi));
    return r;
}
__device__ __forceinline__ void upk2(unsigned long long v, float& lo, float& hi) {
    asm("mov.b64 {%0, %1}, %2;" : "=f"(lo), "=f"(hi) : "l"(v));
}
#define FMA2(d, a, b) asm("fma.rn.f32x2 %0, %1, %2, %0;" : "+l"(d) : "l"(a), "l"(b))

// ============================================================================
// conv1: fused bilinear-2x-upsample + conv3x3(64->64) + bias + BN + ReLU
// grid (2, 64, B*4): tile 128(w) x 4(h), co quarter (16) per block.
// block 256 = 32 xg * 4 yg * 2 cg. thread: 4 px * 8 co (as 4 co-pairs).
// ============================================================================
__global__ __launch_bounds__(256, 2) void k_conv1(
    const float* __restrict__ x,
    const float* __restrict__ w1, const float* __restrict__ b1,
    const float* __restrict__ gamma1, const float* __restrict__ beta1,
    const float* __restrict__ mean1, const float* __restrict__ var1)
{
    __shared__ unsigned long long s_w[CIN][9][8];  // [ci][tap][co-pair] (w2co,w2co+1)
    __shared__ float s_in[2][6][132];
    __shared__ float s_scale[16], s_shift[16];

    const int tid = threadIdx.x;
    const int xg = tid & 31;
    const int yg = (tid >> 5) & 3;
    const int cg = tid >> 7;               // 0/1: which 8-co group of the 16
    const int bz  = blockIdx.z;
    const int b   = bz >> 2;
    const int co0 = (bz & 3) * 16;
    const int x0t = blockIdx.x * 128;
    const int y0t = blockIdx.y * 4;

    const float* xb = x + (size_t)b * CIN * (H1 * W1);

    // ---- preload all weights for this co-quarter (once) ----
    for (int i = tid; i < CIN * 9 * 8; i += 256) {
        int cp = i & 7; int rest = i >> 3;
        int p = rest % 9; int ci = rest / 9;
        int coA = co0 + 2 * cp;
        float wa = w1[((size_t)coA       * CIN + ci) * 9 + p];
        float wb = w1[((size_t)(coA + 1) * CIN + ci) * 9 + p];
        s_w[ci][p][cp] = pk2(wa, wb);
    }
    if (tid < 16) {
        int co = co0 + tid;
        float a = gamma1[co] * rsqrtf(var1[co] + 1e-5f);
        s_scale[tid] = a;
        s_shift[tid] = fmaf(a, b1[co] - mean1[co], beta1[co]);
    }

    // ---- helper lambdas for fused upsample fill ----
    // element i in [0,792): r=i/132, c=i%132 (only c<130 used by compute)
#define COORDS(i, r, c, gy, gx, inb)                                          \
    int r = (i) / 132; int c = (i) - r * 132;                                 \
    int gy = y0t + r - 1; int gx = x0t + c - 1;                               \
    bool inb = (c < 130) && ((i) < 792) &&                                    \
               (gy >= 0) && (gy < H2) && (gx >= 0) && (gx < W2);

    // first buffer fill (ci = 0), direct
    {
        const float* xp = xb;
        for (int i = tid; i < 792; i += 256) {
            COORDS(i, r, c, gy, gx, inb);
            float v = 0.f;
            if (inb) {
                int ys = (gy - 1) >> 1, xs = (gx - 1) >> 1;
                float wy = (gy & 1) ? 0.25f : 0.75f;
                float wx = (gx & 1) ? 0.25f : 0.75f;
                int y0c = max(ys, 0), y1c = min(ys + 1, H1 - 1);
                int x0c = max(xs, 0), x1c = min(xs + 1, W1 - 1);
                float a = xp[y0c * W1 + x0c];
                float bb = xp[y0c * W1 + x1c];
                float cc = xp[y1c * W1 + x0c];
                float d = xp[y1c * W1 + x1c];
                float top = a + wx * (bb - a);
                float bot = cc + wx * (d - cc);
                v = top + wy * (bot - top);
            }
            s_in[0][r][c] = v;
        }
    }
    __syncthreads();

    unsigned long long acc[4][4];
#pragma unroll
    for (int q = 0; q < 4; q++)
#pragma unroll
        for (int j = 0; j < 4; j++) acc[q][j] = 0ull;

    for (int ci = 0; ci < CIN; ci++) {
        const int cur = ci & 1;

        // ---- prefetch raw bilinear source loads for ci+1 (registers) ----
        float lv[16];
        if (ci < CIN - 1) {
            const float* xp = xb + (size_t)(ci + 1) * (H1 * W1);
#pragma unroll
            for (int t = 0; t < 4; t++) {
                int i = tid + t * 256;
                COORDS(i, r, c, gy, gx, inb);
                int ys = (gy - 1) >> 1, xs = (gx - 1) >> 1;
                int y0c = max(ys, 0), y1c = min(ys + 1, H1 - 1);
                int x0c = max(xs, 0), x1c = min(xs + 1, W1 - 1);
                // always-safe addresses (clamped); invalid elems zeroed later
                int base0 = inb ? (y0c * W1) : 0;
                int base1 = inb ? (y1c * W1) : 0;
                int xa = inb ? x0c : 0, xb2 = inb ? x1c : 0;
                lv[4 * t + 0] = xp[base0 + xa];
                lv[4 * t + 1] = xp[base0 + xb2];
                lv[4 * t + 2] = xp[base1 + xa];
                lv[4 * t + 3] = xp[base1 + xb2];
            }
        }

        // ---- compute phase: conv taps from s_in[cur] ----
        unsigned long long P2[3][6];
#pragma unroll
        for (int r = 0; r < 3; r++) {
            const float* row = &s_in[cur][yg + r][4 * xg];
            float4 F = *(const float4*)row;
            float2 G = *(const float2*)(row + 4);
            P2[r][0] = pk2(F.x, F.x);
            P2[r][1] = pk2(F.y, F.y);
            P2[r][2] = pk2(F.z, F.z);
            P2[r][3] = pk2(F.w, F.w);
            P2[r][4] = pk2(G.x, G.x);
            P2[r][5] = pk2(G.y, G.y);
        }

#pragma unroll
        for (int p = 0; p < 9; p++) {
            const int kr = p / 3, kc = p % 3;
            const ulonglong2* wrow = (const ulonglong2*)&s_w[ci][p][cg * 4];
            ulonglong2 wA = wrow[0];
            ulonglong2 wB = wrow[1];
#pragma unroll
            for (int q = 0; q < 4; q++) {
                unsigned long long iv = P2[kr][kc + q];
                FMA2(acc[q][0], iv, wA.x);
                FMA2(acc[q][1], iv, wA.y);
                FMA2(acc[q][2], iv, wB.x);
                FMA2(acc[q][3], iv, wB.y);
            }
        }

        // ---- write phase: finish bilinear, store into other buffer ----
        if (ci < CIN - 1) {
#pragma unroll
            for (int t = 0; t < 4; t++) {
                int i = tid + t * 256;
                COORDS(i, r, c, gy, gx, inb);
                if (i < 792) {
                    float wy = (gy & 1) ? 0.25f : 0.75f;
                    float wx = (gx & 1) ? 0.25f : 0.75f;
                    float a = lv[4 * t + 0], bb = lv[4 * t + 1];
                    float cc = lv[4 * t + 2], d = lv[4 * t + 3];
                    float top = a + wx * (bb - a);
                    float bot = cc + wx * (d - cc);
                    float v = top + wy * (bot - top);
                    s_in[cur ^ 1][r][c] = inb ? v : 0.f;
                }
            }
        }
        __syncthreads();
    }
#undef COORDS

    // ---- epilogue: BN + ReLU, write 8 co planes x 4 px ----
    const int oy = y0t + yg;
    const int ox = x0t + 4 * xg;
    float* outb = g_c1 + (((size_t)b * CIN + co0 + 8 * cg) << 16) + (oy << 8) + ox;
#pragma unroll
    for (int j = 0; j < 4; j++) {
        float va[4], vb[4];
#pragma unroll
        for (int q = 0; q < 4; q++) upk2(acc[q][j], va[q], vb[q]);
        const int cr = 8 * cg + 2 * j;
        const float sa = s_scale[cr],     sha = s_shift[cr];
        const float sb = s_scale[cr + 1], shb = s_shift[cr + 1];
        float4 oa, ob;
        oa.x = fmaxf(fmaf(sa, va[0], sha), 0.f);
        oa.y = fmaxf(fmaf(sa, va[1], sha), 0.f);
        oa.z = fmaxf(fmaf(sa, va[2], sha), 0.f);
        oa.w = fmaxf(fmaf(sa, va[3], sha), 0.f);
        ob.x = fmaxf(fmaf(sb, vb[0], shb), 0.f);
        ob.y = fmaxf(fmaf(sb, vb[1], shb), 0.f);
        ob.z = fmaxf(fmaf(sb, vb[2], shb), 0.f);
        ob.w = fmaxf(fmaf(sb, vb[3], shb), 0.f);
        *(float4*)(outb + ((size_t)(2 * j)     << 16)) = oa;
        *(float4*)(outb + ((size_t)(2 * j + 1) << 16)) = ob;
    }
}

// ---------------- conv1x1(64->8) + BN + threshold (RF=1.0) ------------------
__global__ void k_conv2(const float* __restrict__ w2,
                        const float* __restrict__ gamma2, const float* __restrict__ beta2,
                        const float* __restrict__ mean2, const float* __restrict__ var2)
{
    __shared__ float s_w[512];
    __shared__ float s_scale[8], s_shift[8];
    int tid = threadIdx.x;
    int g = blockIdx.x * 256 + tid;
    if (tid < 8) {
        float a = gamma2[tid] * rsqrtf(var2[tid] + 1e-5f);
        s_scale[tid] = a;
        s_shift[tid] = beta2[tid] - a * mean2[tid];
    }
    for (int i = tid; i < 512; i += 256) s_w[i] = w2[i];
    __syncthreads();

    int b = g >> 16;
    int pix = g & 65535;
    const float* c1 = g_c1 + (size_t)b * CIN * PLANE + pix;
    float acc[8];
#pragma unroll
    for (int co = 0; co < 8; co++) acc[co] = 0.f;
    for (int ci = 0; ci < CIN; ci++) {
        float v = c1[(size_t)ci * PLANE];
#pragma unroll
        for (int co = 0; co < 8; co++) acc[co] += v * s_w[co * 64 + ci];
    }
#pragma unroll
    for (int co = 0; co < 8; co++) {
        float o = fmaf(s_scale[co], acc[co], s_shift[co]);
        g_xf[((size_t)b * COUT + co) * PLANE + pix] = (o > 1.0f) ? o : 0.f;
    }
}

// ---------------- separable 5x5 window sum (zero pad) -----------------------
__global__ void k_rowsum() {
    int gid = blockIdx.x * blockDim.x + threadIdx.x;
    int x = gid & 255;
    int base = gid - x;
    float s = 0.f;
#pragma unroll
    for (int d = -2; d <= 2; d++) {
        int xx = x + d;
        if (xx >= 0 && xx < 256) s += g_xf[base + xx];
    }
    g_rs[gid] = s;
}
__global__ void k_colsum() {
    int gid = blockIdx.x * blockDim.x + threadIdx.x;
    int x = gid & 255;
    int y = (gid >> 8) & 255;
    int pl = gid >> 16;
    float s = 0.f;
#pragma unroll
    for (int d = -2; d <= 2; d++) {
        int yy = y + d;
        if (yy >= 0 && yy < 256) s += g_rs[((size_t)pl << 16) + (yy << 8) + x];
    }
    g_ws[gid] = s;
}

// ---------------- row max of ws ----------------------------------------------
__global__ void k_rowmax() {
    int gid = blockIdx.x * blockDim.x + threadIdx.x;
    int x = gid & 255;
    int base = gid - x;
    float m = -1.f; // ws >= 0 always; reference pads with -inf => exclude OOB
#pragma unroll
    for (int d = -2; d <= 2; d++) {
        int xx = x + d;
        if (xx >= 0 && xx < 256) m = fmaxf(m, g_ws[base + xx]);
    }
    g_rm[gid] = m;
}

// ---------------- fused NMS mask + top-8 per (b, co) ------------------------
// key = (float_bits << 32) | ~index  -> ties break to lowest index (lax.top_k)
__global__ void k_topk() {
    __shared__ unsigned long long s[256 * 8];
    const int bc = blockIdx.x;
    const int x = threadIdx.x;            // one column per thread
    const float* ws = g_ws + (size_t)bc * PLANE;
    const float* rm = g_rm + (size_t)bc * PLANE;

    unsigned long long k[8];
#pragma unroll
    for (int j = 0; j < 8; j++) k[j] = 0ull;

    float w0 = -1.f, w1 = -1.f, w2 = rm[x], w3 = rm[256 + x], w4;
    for (int y = 0; y < 256; y++) {
        w4 = (y + 2 < 256) ? rm[((y + 2) << 8) + x] : -1.f;
        float m = fmaxf(fmaxf(fmaxf(w0, w1), fmaxf(w2, w3)), w4);
        float v = ws[(y << 8) + x];
        if (v == m) {
            unsigned pos = (unsigned)((y << 8) + x);
            unsigned long long key =
                ((unsigned long long)__float_as_uint(v) << 32) | (unsigned)(~pos);
            if (key > k[7]) {
                int p = 7;
#pragma unroll
                for (int q = 7; q > 0; q--) {
                    if (key > k[q - 1]) { k[q] = k[q - 1]; p = q - 1; }
                }
                k[p] = key;
            }
        }
        w0 = w1; w1 = w2; w2 = w3; w3 = w4;
    }
#pragma unroll
    for (int j = 0; j < 8; j++) s[x * 8 + j] = k[j];
    __syncthreads();

    for (int off = 128; off > 0; off >>= 1) {
        if (x < off) {
            unsigned long long* a = &s[x * 8];
            unsigned long long* b = &s[(x + off) * 8];
            unsigned long long out[8];
            int i = 0, j = 0;
#pragma unroll
            for (int t = 0; t < 8; t++)
                out[t] = (a[i] >= b[j]) ? a[i++] : b[j++];
#pragma unroll
            for (int t = 0; t < 8; t++) a[t] = out[t];
        }
        __syncthreads();
    }
    if (x < 8) {
        unsigned pos = ~(unsigned)(s[x] & 0xFFFFFFFFull);
        g_topidx[bc * 8 + x] = (int)pos;
    }
}

// ---------------- gather 5x5 patches + positions -----------------------------
__global__ void k_gather(float* __restrict__ out) {
    int gid = blockIdx.x * blockDim.x + threadIdx.x;
    if (gid >= B_ * COUT * NUM_) return;
    int bc = gid >> 3;
    int pos = g_topidx[gid];
    int h = pos >> 8, w = pos & 255;
    const float* xf = g_xf + (size_t)bc * PLANE;
    float* po = out + gid * 25;
#pragma unroll
    for (int dy = 0; dy < 5; dy++) {
        int yy = h + dy - 2;
#pragma unroll
        for (int dx = 0; dx < 5; dx++) {
            int xx = w + dx - 2;
            float v = 0.f;
            if (yy >= 0 && yy < 256 && xx >= 0 && xx < 256) v = xf[yy * 256 + xx];
            po[dy * 5 + dx] = v;
        }
    }
    float* pp = out + B_ * COUT * NUM_ * 25 + gid * 4;
    pp[0] = (float)min(max(w - 2, 0), 255);
    pp[1] = (float)min(max(h - 2, 0), 255);
    pp[2] = (float)min(max(w + 2, 0), 255);
    pp[3] = (float)min(max(h + 2, 0), 255);
}

// ---------------- launch ------------------------------------------------------
extern "C" void kernel_launch(void* const* d_in, const int* in_sizes, int n_in,
                              void* d_out, int out_size) {
    const float* x      = (const float*)d_in[0];
    const float* w1     = (const float*)d_in[1];
    const float* b1     = (const float*)d_in[2];
    const float* gamma1 = (const float*)d_in[3];
    const float* beta1  = (const float*)d_in[4];
    const float* mean1  = (const float*)d_in[5];
    const float* var1   = (const float*)d_in[6];
    const float* w2     = (const float*)d_in[7];
    const float* gamma2 = (const float*)d_in[8];
    const float* beta2  = (const float*)d_in[9];
    const float* mean2  = (const float*)d_in[10];
    const float* var2   = (const float*)d_in[11];
    float* out = (float*)d_out;

    dim3 cg(2, 64, B_ * 4);
    k_conv1<<<cg, 256>>>(x, w1, b1, gamma1, beta1, mean1, var1);

    k_conv2<<<(B_ * PLANE) / 256, 256>>>(w2, gamma2, beta2, mean2, var2);

    const int n = B_ * COUT * PLANE;
    k_rowsum<<<n / 256, 256>>>();
    k_colsum<<<n / 256, 256>>>();
    k_rowmax<<<n / 256, 256>>>();

    k_topk<<<B_ * COUT, 256>>>();
    k_gather<<<2, 256>>>(out);
}

// round 4
// speedup vs baseline: 2.0651x; 1.2636x over previous
#include <cuda_runtime.h>
#include <cstdint>

#define B_   8
#define CIN  64
#define COUT 8
#define H1   128
#define W1   128
#define H2   256
#define W2   256
#define PLANE (H2*W2)   /* 65536 */
#define NUM_ 8

// ---------------- scratch (device globals; no allocation allowed) ----------
__device__ float g_c1 [(size_t)B_*CIN *PLANE];  // conv1+BN+ReLU
__device__ float g_xf [(size_t)B_*COUT*PLANE];  // conv2+BN, thresholded
__device__ float g_rs [(size_t)B_*COUT*PLANE];  // row sums
__device__ float g_ws [(size_t)B_*COUT*PLANE];  // 5x5 window sums
__device__ float g_rm [(size_t)B_*COUT*PLANE];  // row max of ws
__device__ int   g_topidx[B_*COUT*NUM_];

// ---------------- packed f32x2 helpers --------------------------------------
__device__ __forceinline__ unsigned long long pk2(float lo, float hi) {
    unsigned long long r;
    asm("mov.b64 %0, {%1, %2};" : "=l"(r) : "f"(lo), "f"(hi));
    return r;
}
__device__ __forceinline__ void upk2(unsigned long long v, float& lo, float& hi) {
    asm("mov.b64 {%0, %1}, %2;" : "=f"(lo), "=f"(hi) : "l"(v));
}
#define FMA2(d, a, b) asm("fma.rn.f32x2 %0, %1, %2, %0;" : "+l"(d) : "l"(a), "l"(b))

// ============================================================================
// conv1: fused bilinear-2x-upsample + conv3x3(64->64) + bias + BN + ReLU
// grid (2, 64, B*4): tile 128(w) x 4(h), co quarter (16) per block.
// block 256 = 32 xg * 4 yg * 2 cg. thread: 4 px * 8 co (4 co-pairs, FFMA2).
// Fill: 198 "runs" of 4 upsampled pixels, 6 source LDGs per run.
// ============================================================================
__global__ __launch_bounds__(256, 3) void k_conv1(
    const float* __restrict__ x,
    const float* __restrict__ w1, const float* __restrict__ b1,
    const float* __restrict__ gamma1, const float* __restrict__ beta1,
    const float* __restrict__ mean1, const float* __restrict__ var1)
{
    __shared__ unsigned long long s_w[CIN][9][8];  // [ci][tap][co-pair]
    __shared__ float s_in[2][6][136];
    __shared__ float s_scale[16], s_shift[16];

    const int tid = threadIdx.x;
    const int xg = tid & 31;
    const int yg = (tid >> 5) & 3;
    const int cg = tid >> 7;               // 0/1: which 8-co group of the 16
    const int bz  = blockIdx.z;
    const int b   = bz >> 2;
    const int co0 = (bz & 3) * 16;
    const int x0t = blockIdx.x * 128;
    const int y0t = blockIdx.y * 4;

    const float* xb = x + (size_t)b * CIN * (H1 * W1);

    // ---- preload all weights for this co-quarter (once) ----
    for (int i = tid; i < CIN * 9 * 8; i += 256) {
        int cp = i & 7; int rest = i >> 3;
        int p = rest % 9; int ci = rest / 9;
        int coA = co0 + 2 * cp;
        float wa = w1[((size_t)coA       * CIN + ci) * 9 + p];
        float wb = w1[((size_t)(coA + 1) * CIN + ci) * 9 + p];
        s_w[ci][p][cp] = pk2(wa, wb);
    }
    if (tid < 16) {
        int co = co0 + tid;
        float a = gamma1[co] * rsqrtf(var1[co] + 1e-5f);
        s_scale[tid] = a;
        s_shift[tid] = fmaf(a, b1[co] - mean1[co], beta1[co]);
    }

    // ---- per-thread run geometry (198 runs: 6 rows x 33 runs of 4 px) ----
    const bool runA = tid < 198;
    const int ur  = tid / 33;                  // 0..5 upsampled row
    const int c0r = (tid - ur * 33) * 4;       // 0..128 col start
    const int gy  = y0t + ur - 1;
    const int gx0 = x0t + c0r - 1;             // odd
    const int sy  = (gy - 1) >> 1;
    const int ro0 = min(max(sy, 0), H1 - 1) * W1;
    const int ro1 = min(max(sy + 1, 0), H1 - 1) * W1;
    const float wyv = (gy & 1) ? 0.25f : 0.75f;
    const int S   = (gx0 - 1) >> 1;
    const int cS0 = min(max(S, 0), W1 - 1);
    const int cS1 = min(max(S + 1, 0), W1 - 1);
    const int cS2 = min(max(S + 2, 0), W1 - 1);
    const bool rowOK = (gy >= 0) && (gy < H2);
    bool mok[4];
#pragma unroll
    for (int j = 0; j < 4; j++) {
        int gx = gx0 + j;
        mok[j] = rowOK && (gx >= 0) && (gx < W2);
    }

#define BILIN(buf, p0a, p0b, p0c, p1a, p1b, p1c) do {                         \
        float t0 = p0a + 0.25f * (p0b - p0a);                                 \
        float t1 = p0a + 0.75f * (p0b - p0a);                                 \
        float t2 = p0b + 0.25f * (p0c - p0b);                                 \
        float t3 = p0b + 0.75f * (p0c - p0b);                                 \
        float u0 = p1a + 0.25f * (p1b - p1a);                                 \
        float u1 = p1a + 0.75f * (p1b - p1a);                                 \
        float u2 = p1b + 0.25f * (p1c - p1b);                                 \
        float u3 = p1b + 0.75f * (p1c - p1b);                                 \
        float4 o;                                                             \
        o.x = mok[0] ? (t0 + wyv * (u0 - t0)) : 0.f;                          \
        o.y = mok[1] ? (t1 + wyv * (u1 - t1)) : 0.f;                          \
        o.z = mok[2] ? (t2 + wyv * (u2 - t2)) : 0.f;                          \
        o.w = mok[3] ? (t3 + wyv * (u3 - t3)) : 0.f;                          \
        *(float4*)&s_in[buf][ur][c0r] = o;                                    \
    } while (0)

    // ---- initial fill (ci = 0) ----
    if (runA) {
        const float* xp = xb;
        float a0 = xp[ro0 + cS0], a1 = xp[ro0 + cS1], a2 = xp[ro0 + cS2];
        float b0 = xp[ro1 + cS0], b1v = xp[ro1 + cS1], b2 = xp[ro1 + cS2];
        BILIN(0, a0, a1, a2, b0, b1v, b2);
    }
    __syncthreads();

    unsigned long long acc[4][4];
#pragma unroll
    for (int q = 0; q < 4; q++)
#pragma unroll
        for (int j = 0; j < 4; j++) acc[q][j] = 0ull;

    for (int ci = 0; ci < CIN; ci++) {
        const int cur = ci & 1;

        // prefetch raw sources for ci+1 into registers
        float p0a, p0b, p0c, p1a, p1b, p1c;
        if (runA && ci < CIN - 1) {
            const float* xp = xb + ((size_t)(ci + 1) << 14);
            p0a = xp[ro0 + cS0]; p0b = xp[ro0 + cS1]; p0c = xp[ro0 + cS2];
            p1a = xp[ro1 + cS0]; p1b = xp[ro1 + cS1]; p1c = xp[ro1 + cS2];
        }

        // ---- compute: row-wise tap loop ----
#pragma unroll
        for (int kr = 0; kr < 3; kr++) {
            const float* row = &s_in[cur][yg + kr][4 * xg];
            float4 F = *(const float4*)row;
            float2 G = *(const float2*)(row + 4);
            unsigned long long Q[6];
            Q[0] = pk2(F.x, F.x);
            Q[1] = pk2(F.y, F.y);
            Q[2] = pk2(F.z, F.z);
            Q[3] = pk2(F.w, F.w);
            Q[4] = pk2(G.x, G.x);
            Q[5] = pk2(G.y, G.y);
#pragma unroll
            for (int kc = 0; kc < 3; kc++) {
                const ulonglong2* wrow =
                    (const ulonglong2*)&s_w[ci][kr * 3 + kc][cg * 4];
                ulonglong2 wA = wrow[0];
                ulonglong2 wB = wrow[1];
#pragma unroll
                for (int q = 0; q < 4; q++) {
                    unsigned long long iv = Q[kc + q];
                    FMA2(acc[q][0], iv, wA.x);
                    FMA2(acc[q][1], iv, wA.y);
                    FMA2(acc[q][2], iv, wB.x);
                    FMA2(acc[q][3], iv, wB.y);
                }
            }
        }

        // ---- finish bilinear for ci+1, store into other buffer ----
        if (runA && ci < CIN - 1) {
            BILIN(cur ^ 1, p0a, p0b, p0c, p1a, p1b, p1c);
        }
        __syncthreads();
    }
#undef BILIN

    // ---- epilogue: BN + ReLU, write 8 co planes x 4 px ----
    const int oy = y0t + yg;
    const int ox = x0t + 4 * xg;
    float* outb = g_c1 + (((size_t)b * CIN + co0 + 8 * cg) << 16) + (oy << 8) + ox;
#pragma unroll
    for (int j = 0; j < 4; j++) {
        float va[4], vb[4];
#pragma unroll
        for (int q = 0; q < 4; q++) upk2(acc[q][j], va[q], vb[q]);
        const int cr = 8 * cg + 2 * j;
        const float sa = s_scale[cr],     sha = s_shift[cr];
        const float sb = s_scale[cr + 1], shb = s_shift[cr + 1];
        float4 oa, ob;
        oa.x = fmaxf(fmaf(sa, va[0], sha), 0.f);
        oa.y = fmaxf(fmaf(sa, va[1], sha), 0.f);
        oa.z = fmaxf(fmaf(sa, va[2], sha), 0.f);
        oa.w = fmaxf(fmaf(sa, va[3], sha), 0.f);
        ob.x = fmaxf(fmaf(sb, vb[0], shb), 0.f);
        ob.y = fmaxf(fmaf(sb, vb[1], shb), 0.f);
        ob.z = fmaxf(fmaf(sb, vb[2], shb), 0.f);
        ob.w = fmaxf(fmaf(sb, vb[3], shb), 0.f);
        *(float4*)(outb + ((size_t)(2 * j)     << 16)) = oa;
        *(float4*)(outb + ((size_t)(2 * j + 1) << 16)) = ob;
    }
}

// ---------------- conv1x1(64->8) + BN + threshold + fused row-sum -----------
// one block per (b, y) row; 256 threads = 256 columns
__global__ __launch_bounds__(256) void k_conv2rs(
    const float* __restrict__ w2,
    const float* __restrict__ gamma2, const float* __restrict__ beta2,
    const float* __restrict__ mean2, const float* __restrict__ var2)
{
    __shared__ float s_w[512];
    __shared__ float s_scale[8], s_shift[8];
    __shared__ float s_xf[8][260];
    const int tid = threadIdx.x;
    const int row = blockIdx.x;
    const int b = row >> 8;
    const int y = row & 255;

    if (tid < 8) {
        float a = gamma2[tid] * rsqrtf(var2[tid] + 1e-5f);
        s_scale[tid] = a;
        s_shift[tid] = beta2[tid] - a * mean2[tid];
        s_xf[tid][0] = s_xf[tid][1] = 0.f;
        s_xf[tid][258] = s_xf[tid][259] = 0.f;
    }
    for (int i = tid; i < 512; i += 256) s_w[i] = w2[i];
    __syncthreads();

    const float* c1 = g_c1 + ((size_t)b * CIN << 16) + (y << 8) + tid;
    float acc[8];
#pragma unroll
    for (int co = 0; co < 8; co++) acc[co] = 0.f;
    for (int ci = 0; ci < CIN; ci++) {
        float v = c1[(size_t)ci << 16];
#pragma unroll
        for (int co = 0; co < 8; co++) acc[co] += v * s_w[co * 64 + ci];
    }
#pragma unroll
    for (int co = 0; co < 8; co++) {
        float o = fmaf(s_scale[co], acc[co], s_shift[co]);
        float xf = (o > 1.0f) ? o : 0.f;
        g_xf[(((size_t)b * COUT + co) << 16) + (y << 8) + tid] = xf;
        s_xf[co][tid + 2] = xf;
    }
    __syncthreads();

#pragma unroll
    for (int co = 0; co < 8; co++) {
        float s = s_xf[co][tid] + s_xf[co][tid + 1] + s_xf[co][tid + 2]
                + s_xf[co][tid + 3] + s_xf[co][tid + 4];
        g_rs[(((size_t)b * COUT + co) << 16) + (y << 8) + tid] = s;
    }
}

// ---------------- fused column-sum (-> ws) + row-max of ws ------------------
// one block per (plane, y) row
__global__ __launch_bounds__(256) void k_wsmax() {
    __shared__ float sw[260];
    const int tid = threadIdx.x;
    const int id = blockIdx.x;
    const int pl = id >> 8;
    const int y = id & 255;
    const float* rs = g_rs + ((size_t)pl << 16);

    float s = 0.f;
#pragma unroll
    for (int d = -2; d <= 2; d++) {
        int yy = y + d;
        if (yy >= 0 && yy < 256) s += rs[(yy << 8) + tid];
    }
    if (tid < 2) { sw[tid] = -1.f; sw[258 + tid] = -1.f; }
    sw[tid + 2] = s;
    g_ws[((size_t)pl << 16) + (y << 8) + tid] = s;
    __syncthreads();

    float m = fmaxf(fmaxf(fmaxf(sw[tid], sw[tid + 1]), fmaxf(sw[tid + 2], sw[tid + 3])),
                    sw[tid + 4]);
    g_rm[((size_t)pl << 16) + (y << 8) + tid] = m;
}

// ---------------- fused NMS mask + top-8 per (b, co) ------------------------
// key = (float_bits << 32) | ~index  -> ties break to lowest index (lax.top_k)
__global__ void k_topk() {
    __shared__ unsigned long long s[256 * 8];
    const int bc = blockIdx.x;
    const int x = threadIdx.x;            // one column per thread
    const float* ws = g_ws + (size_t)bc * PLANE;
    const float* rm = g_rm + (size_t)bc * PLANE;

    unsigned long long k[8];
#pragma unroll
    for (int j = 0; j < 8; j++) k[j] = 0ull;

    float w0 = -1.f, w1 = -1.f, w2 = rm[x], w3 = rm[256 + x], w4;
    for (int y = 0; y < 256; y++) {
        w4 = (y + 2 < 256) ? rm[((y + 2) << 8) + x] : -1.f;
        float m = fmaxf(fmaxf(fmaxf(w0, w1), fmaxf(w2, w3)), w4);
        float v = ws[(y << 8) + x];
        if (v == m) {
            unsigned pos = (unsigned)((y << 8) + x);
            unsigned long long key =
                ((unsigned long long)__float_as_uint(v) << 32) | (unsigned)(~pos);
            if (key > k[7]) {
                int p = 7;
#pragma unroll
                for (int q = 7; q > 0; q--) {
                    if (key > k[q - 1]) { k[q] = k[q - 1]; p = q - 1; }
                }
                k[p] = key;
            }
        }
        w0 = w1; w1 = w2; w2 = w3; w3 = w4;
    }
#pragma unroll
    for (int j = 0; j < 8; j++) s[x * 8 + j] = k[j];
    __syncthreads();

    for (int off = 128; off > 0; off >>= 1) {
        if (x < off) {
            unsigned long long* a = &s[x * 8];
            unsigned long long* b = &s[(x + off) * 8];
            unsigned long long out[8];
            int i = 0, j = 0;
#pragma unroll
            for (int t = 0; t < 8; t++)
                out[t] = (a[i] >= b[j]) ? a[i++] : b[j++];
#pragma unroll
            for (int t = 0; t < 8; t++) a[t] = out[t];
        }
        __syncthreads();
    }
    if (x < 8) {
        unsigned pos = ~(unsigned)(s[x] & 0xFFFFFFFFull);
        g_topidx[bc * 8 + x] = (int)pos;
    }
}

// ---------------- gather 5x5 patches + positions -----------------------------
__global__ void k_gather(float* __restrict__ out) {
    int gid = blockIdx.x * blockDim.x + threadIdx.x;
    if (gid >= B_ * COUT * NUM_) return;
    int bc = gid >> 3;
    int pos = g_topidx[gid];
    int h = pos >> 8, w = pos & 255;
    const float* xf = g_xf + (size_t)bc * PLANE;
    float* po = out + gid * 25;
#pragma unroll
    for (int dy = 0; dy < 5; dy++) {
        int yy = h + dy - 2;
#pragma unroll
        for (int dx = 0; dx < 5; dx++) {
            int xx = w + dx - 2;
            float v = 0.f;
            if (yy >= 0 && yy < 256 && xx >= 0 && xx < 256) v = xf[yy * 256 + xx];
            po[dy * 5 + dx] = v;
        }
    }
    float* pp = out + B_ * COUT * NUM_ * 25 + gid * 4;
    pp[0] = (float)min(max(w - 2, 0), 255);
    pp[1] = (float)min(max(h - 2, 0), 255);
    pp[2] = (float)min(max(w + 2, 0), 255);
    pp[3] = (float)min(max(h + 2, 0), 255);
}

// ---------------- launch ------------------------------------------------------
extern "C" void kernel_launch(void* const* d_in, const int* in_sizes, int n_in,
                              void* d_out, int out_size) {
    const float* x      = (const float*)d_in[0];
    const float* w1     = (const float*)d_in[1];
    const float* b1     = (const float*)d_in[2];
    const float* gamma1 = (const float*)d_in[3];
    const float* beta1  = (const float*)d_in[4];
    const float* mean1  = (const float*)d_in[5];
    const float* var1   = (const float*)d_in[6];
    const float* w2     = (const float*)d_in[7];
    const float* gamma2 = (const float*)d_in[8];
    const float* beta2  = (const float*)d_in[9];
    const float* mean2  = (const float*)d_in[10];
    const float* var2   = (const float*)d_in[11];
    float* out = (float*)d_out;

    dim3 cg(2, 64, B_ * 4);
    k_conv1<<<cg, 256>>>(x, w1, b1, gamma1, beta1, mean1, var1);

    k_conv2rs<<<B_ * 256, 256>>>(w2, gamma2, beta2, mean2, var2);
    k_wsmax<<<B_ * COUT * 256, 256>>>();

    k_topk<<<B_ * COUT, 256>>>();
    k_gather<<<2, 256>>>(out);
}

// round 5
// speedup vs baseline: 2.1344x; 1.0336x over previous
#include <cuda_runtime.h>
#include <cstdint>

#define B_   8
#define CIN  64
#define COUT 8
#define H1   128
#define W1   128
#define H2   256
#define W2   256
#define PLANE (H2*W2)   /* 65536 */
#define NUM_ 8

// ---------------- scratch (device globals; no allocation allowed) ----------
__device__ float g_c1 [(size_t)B_*CIN *PLANE];  // conv1+BN+ReLU
__device__ float g_xf [(size_t)B_*COUT*PLANE];  // conv2+BN, thresholded
__device__ float g_rs [(size_t)B_*COUT*PLANE];  // row sums
__device__ float g_ws [(size_t)B_*COUT*PLANE];  // 5x5 window sums
__device__ float g_rm [(size_t)B_*COUT*PLANE];  // row max of ws
__device__ unsigned long long g_seg[B_*COUT*8*8]; // per-segment top-8 keys

// ---------------- packed f32x2 helpers --------------------------------------
__device__ __forceinline__ unsigned long long pk2(float lo, float hi) {
    unsigned long long r;
    asm("mov.b64 %0, {%1, %2};" : "=l"(r) : "f"(lo), "f"(hi));
    return r;
}
__device__ __forceinline__ void upk2(unsigned long long v, float& lo, float& hi) {
    asm("mov.b64 {%0, %1}, %2;" : "=f"(lo), "=f"(hi) : "l"(v));
}
#define FMA2(d, a, b) asm("fma.rn.f32x2 %0, %1, %2, %0;" : "+l"(d) : "l"(a), "l"(b))

// ============================================================================
// conv1: fused bilinear-2x-upsample + conv3x3(64->64) + bias + BN + ReLU
// ============================================================================
__global__ __launch_bounds__(256, 3) void k_conv1(
    const float* __restrict__ x,
    const float* __restrict__ w1, const float* __restrict__ b1,
    const float* __restrict__ gamma1, const float* __restrict__ beta1,
    const float* __restrict__ mean1, const float* __restrict__ var1)
{
    __shared__ unsigned long long s_w[CIN][9][8];  // [ci][tap][co-pair]
    __shared__ float s_in[2][6][136];
    __shared__ float s_scale[16], s_shift[16];

    const int tid = threadIdx.x;
    const int xg = tid & 31;
    const int yg = (tid >> 5) & 3;
    const int cg = tid >> 7;
    const int bz  = blockIdx.z;
    const int b   = bz >> 2;
    const int co0 = (bz & 3) * 16;
    const int x0t = blockIdx.x * 128;
    const int y0t = blockIdx.y * 4;

    const float* xb = x + (size_t)b * CIN * (H1 * W1);

    for (int i = tid; i < CIN * 9 * 8; i += 256) {
        int cp = i & 7; int rest = i >> 3;
        int p = rest % 9; int ci = rest / 9;
        int coA = co0 + 2 * cp;
        float wa = w1[((size_t)coA       * CIN + ci) * 9 + p];
        float wb = w1[((size_t)(coA + 1) * CIN + ci) * 9 + p];
        s_w[ci][p][cp] = pk2(wa, wb);
    }
    if (tid < 16) {
        int co = co0 + tid;
        float a = gamma1[co] * rsqrtf(var1[co] + 1e-5f);
        s_scale[tid] = a;
        s_shift[tid] = fmaf(a, b1[co] - mean1[co], beta1[co]);
    }

    const bool runA = tid < 198;
    const int ur  = tid / 33;
    const int c0r = (tid - ur * 33) * 4;
    const int gy  = y0t + ur - 1;
    const int gx0 = x0t + c0r - 1;
    const int sy  = (gy - 1) >> 1;
    const int ro0 = min(max(sy, 0), H1 - 1) * W1;
    const int ro1 = min(max(sy + 1, 0), H1 - 1) * W1;
    const float wyv = (gy & 1) ? 0.25f : 0.75f;
    const int S   = (gx0 - 1) >> 1;
    const int cS0 = min(max(S, 0), W1 - 1);
    const int cS1 = min(max(S + 1, 0), W1 - 1);
    const int cS2 = min(max(S + 2, 0), W1 - 1);
    const bool rowOK = (gy >= 0) && (gy < H2);
    bool mok[4];
#pragma unroll
    for (int j = 0; j < 4; j++) {
        int gx = gx0 + j;
        mok[j] = rowOK && (gx >= 0) && (gx < W2);
    }

#define BILIN(buf, p0a, p0b, p0c, p1a, p1b, p1c) do {                         \
        float t0 = p0a + 0.25f * (p0b - p0a);                                 \
        float t1 = p0a + 0.75f * (p0b - p0a);                                 \
        float t2 = p0b + 0.25f * (p0c - p0b);                                 \
        float t3 = p0b + 0.75f * (p0c - p0b);                                 \
        float u0 = p1a + 0.25f * (p1b - p1a);                                 \
        float u1 = p1a + 0.75f * (p1b - p1a);                                 \
        float u2 = p1b + 0.25f * (p1c - p1b);                                 \
        float u3 = p1b + 0.75f * (p1c - p1b);                                 \
        float4 o;                                                             \
        o.x = mok[0] ? (t0 + wyv * (u0 - t0)) : 0.f;                          \
        o.y = mok[1] ? (t1 + wyv * (u1 - t1)) : 0.f;                          \
        o.z = mok[2] ? (t2 + wyv * (u2 - t2)) : 0.f;                          \
        o.w = mok[3] ? (t3 + wyv * (u3 - t3)) : 0.f;                          \
        *(float4*)&s_in[buf][ur][c0r] = o;                                    \
    } while (0)

    if (runA) {
        const float* xp = xb;
        float a0 = xp[ro0 + cS0], a1 = xp[ro0 + cS1], a2 = xp[ro0 + cS2];
        float b0 = xp[ro1 + cS0], b1v = xp[ro1 + cS1], b2 = xp[ro1 + cS2];
        BILIN(0, a0, a1, a2, b0, b1v, b2);
    }
    __syncthreads();

    unsigned long long acc[4][4];
#pragma unroll
    for (int q = 0; q < 4; q++)
#pragma unroll
        for (int j = 0; j < 4; j++) acc[q][j] = 0ull;

    for (int ci = 0; ci < CIN; ci++) {
        const int cur = ci & 1;

        float p0a, p0b, p0c, p1a, p1b, p1c;
        if (runA && ci < CIN - 1) {
            const float* xp = xb + ((size_t)(ci + 1) << 14);
            p0a = xp[ro0 + cS0]; p0b = xp[ro0 + cS1]; p0c = xp[ro0 + cS2];
            p1a = xp[ro1 + cS0]; p1b = xp[ro1 + cS1]; p1c = xp[ro1 + cS2];
        }

#pragma unroll
        for (int kr = 0; kr < 3; kr++) {
            const float* row = &s_in[cur][yg + kr][4 * xg];
            float4 F = *(const float4*)row;
            float2 G = *(const float2*)(row + 4);
            unsigned long long Q[6];
            Q[0] = pk2(F.x, F.x);
            Q[1] = pk2(F.y, F.y);
            Q[2] = pk2(F.z, F.z);
            Q[3] = pk2(F.w, F.w);
            Q[4] = pk2(G.x, G.x);
            Q[5] = pk2(G.y, G.y);
#pragma unroll
            for (int kc = 0; kc < 3; kc++) {
                const ulonglong2* wrow =
                    (const ulonglong2*)&s_w[ci][kr * 3 + kc][cg * 4];
                ulonglong2 wA = wrow[0];
                ulonglong2 wB = wrow[1];
#pragma unroll
                for (int q = 0; q < 4; q++) {
                    unsigned long long iv = Q[kc + q];
                    FMA2(acc[q][0], iv, wA.x);
                    FMA2(acc[q][1], iv, wA.y);
                    FMA2(acc[q][2], iv, wB.x);
                    FMA2(acc[q][3], iv, wB.y);
                }
            }
        }

        if (runA && ci < CIN - 1) {
            BILIN(cur ^ 1, p0a, p0b, p0c, p1a, p1b, p1c);
        }
        __syncthreads();
    }
#undef BILIN

    const int oy = y0t + yg;
    const int ox = x0t + 4 * xg;
    float* outb = g_c1 + (((size_t)b * CIN + co0 + 8 * cg) << 16) + (oy << 8) + ox;
#pragma unroll
    for (int j = 0; j < 4; j++) {
        float va[4], vb[4];
#pragma unroll
        for (int q = 0; q < 4; q++) upk2(acc[q][j], va[q], vb[q]);
        const int cr = 8 * cg + 2 * j;
        const float sa = s_scale[cr],     sha = s_shift[cr];
        const float sb = s_scale[cr + 1], shb = s_shift[cr + 1];
        float4 oa, ob;
        oa.x = fmaxf(fmaf(sa, va[0], sha), 0.f);
        oa.y = fmaxf(fmaf(sa, va[1], sha), 0.f);
        oa.z = fmaxf(fmaf(sa, va[2], sha), 0.f);
        oa.w = fmaxf(fmaf(sa, va[3], sha), 0.f);
        ob.x = fmaxf(fmaf(sb, vb[0], shb), 0.f);
        ob.y = fmaxf(fmaf(sb, vb[1], shb), 0.f);
        ob.z = fmaxf(fmaf(sb, vb[2], shb), 0.f);
        ob.w = fmaxf(fmaf(sb, vb[3], shb), 0.f);
        *(float4*)(outb + ((size_t)(2 * j)     << 16)) = oa;
        *(float4*)(outb + ((size_t)(2 * j + 1) << 16)) = ob;
    }
}

// ---------------- conv1x1(64->8) + BN + threshold + fused row-sum -----------
__global__ __launch_bounds__(256) void k_conv2rs(
    const float* __restrict__ w2,
    const float* __restrict__ gamma2, const float* __restrict__ beta2,
    const float* __restrict__ mean2, const float* __restrict__ var2)
{
    __shared__ float s_w[512];
    __shared__ float s_scale[8], s_shift[8];
    __shared__ float s_xf[8][260];
    const int tid = threadIdx.x;
    const int row = blockIdx.x;
    const int b = row >> 8;
    const int y = row & 255;

    if (tid < 8) {
        float a = gamma2[tid] * rsqrtf(var2[tid] + 1e-5f);
        s_scale[tid] = a;
        s_shift[tid] = beta2[tid] - a * mean2[tid];
        s_xf[tid][0] = s_xf[tid][1] = 0.f;
        s_xf[tid][258] = s_xf[tid][259] = 0.f;
    }
    for (int i = tid; i < 512; i += 256) s_w[i] = w2[i];
    __syncthreads();

    const float* c1 = g_c1 + ((size_t)b * CIN << 16) + (y << 8) + tid;
    float acc[8];
#pragma unroll
    for (int co = 0; co < 8; co++) acc[co] = 0.f;
    for (int ci = 0; ci < CIN; ci++) {
        float v = c1[(size_t)ci << 16];
#pragma unroll
        for (int co = 0; co < 8; co++) acc[co] += v * s_w[co * 64 + ci];
    }
#pragma unroll
    for (int co = 0; co < 8; co++) {
        float o = fmaf(s_scale[co], acc[co], s_shift[co]);
        float xf = (o > 1.0f) ? o : 0.f;
        g_xf[(((size_t)b * COUT + co) << 16) + (y << 8) + tid] = xf;
        s_xf[co][tid + 2] = xf;
    }
    __syncthreads();

#pragma unroll
    for (int co = 0; co < 8; co++) {
        float s = s_xf[co][tid] + s_xf[co][tid + 1] + s_xf[co][tid + 2]
                + s_xf[co][tid + 3] + s_xf[co][tid + 4];
        g_rs[(((size_t)b * COUT + co) << 16) + (y << 8) + tid] = s;
    }
}

// ---------------- fused column-sum (-> ws) + row-max of ws ------------------
__global__ __launch_bounds__(256) void k_wsmax() {
    __shared__ float sw[260];
    const int tid = threadIdx.x;
    const int id = blockIdx.x;
    const int pl = id >> 8;
    const int y = id & 255;
    const float* rs = g_rs + ((size_t)pl << 16);

    float s = 0.f;
#pragma unroll
    for (int d = -2; d <= 2; d++) {
        int yy = y + d;
        if (yy >= 0 && yy < 256) s += rs[(yy << 8) + tid];
    }
    if (tid < 2) { sw[tid] = -1.f; sw[258 + tid] = -1.f; }
    sw[tid + 2] = s;
    g_ws[((size_t)pl << 16) + (y << 8) + tid] = s;
    __syncthreads();

    float m = fmaxf(fmaxf(fmaxf(sw[tid], sw[tid + 1]), fmaxf(sw[tid + 2], sw[tid + 3])),
                    sw[tid + 4]);
    g_rm[((size_t)pl << 16) + (y << 8) + tid] = m;
}

// ---------------- top-k stage 1: per-segment top-8 ---------------------------
// grid = 64 planes * 8 segments of 32 rows. key = (bits<<32) | ~pos.
__global__ __launch_bounds__(256) void k_topk1() {
    __shared__ unsigned long long s[256 * 8];
    const int bid = blockIdx.x;
    const int bc = bid >> 3;
    const int seg = bid & 7;
    const int y0 = seg * 32;
    const int x = threadIdx.x;
    const float* ws = g_ws + (size_t)bc * PLANE;
    const float* rm = g_rm + (size_t)bc * PLANE;

    unsigned long long k[8];
#pragma unroll
    for (int j = 0; j < 8; j++) k[j] = 0ull;

    float w0 = (y0 - 2 >= 0) ? rm[((y0 - 2) << 8) + x] : -1.f;
    float w1 = (y0 - 1 >= 0) ? rm[((y0 - 1) << 8) + x] : -1.f;
    float w2 = rm[(y0 << 8) + x];
    float w3 = rm[((y0 + 1) << 8) + x];
    float w4;
    for (int i = 0; i < 32; i++) {
        const int y = y0 + i;
        w4 = (y + 2 < 256) ? rm[((y + 2) << 8) + x] : -1.f;
        float m = fmaxf(fmaxf(fmaxf(w0, w1), fmaxf(w2, w3)), w4);
        float v = ws[(y << 8) + x];
        if (v == m) {
            unsigned pos = (unsigned)((y << 8) + x);
            unsigned long long key =
                ((unsigned long long)__float_as_uint(v) << 32) | (unsigned)(~pos);
            if (key > k[7]) {
                int p = 7;
#pragma unroll
                for (int q = 7; q > 0; q--) {
                    if (key > k[q - 1]) { k[q] = k[q - 1]; p = q - 1; }
                }
                k[p] = key;
            }
        }
        w0 = w1; w1 = w2; w2 = w3; w3 = w4;
    }
#pragma unroll
    for (int j = 0; j < 8; j++) s[x * 8 + j] = k[j];
    __syncthreads();

    for (int off = 128; off > 0; off >>= 1) {
        if (x < off) {
            unsigned long long* a = &s[x * 8];
            unsigned long long* b = &s[(x + off) * 8];
            unsigned long long out[8];
            int i = 0, j = 0;
#pragma unroll
            for (int t = 0; t < 8; t++)
                out[t] = (a[i] >= b[j]) ? a[i++] : b[j++];
#pragma unroll
            for (int t = 0; t < 8; t++) a[t] = out[t];
        }
        __syncthreads();
    }
    if (x < 8) g_seg[bid * 8 + x] = s[x];
}

// ---------------- top-k stage 2 (merge 8x8 keys) + fused gather --------------
// 64 blocks (one per plane) x 64 threads.
__global__ __launch_bounds__(64) void k_topk2(float* __restrict__ out) {
    __shared__ unsigned long long s[64];
    __shared__ unsigned long long top[8];
    const int bc = blockIdx.x;
    const int tid = threadIdx.x;

    s[tid] = g_seg[bc * 64 + tid];
    __syncthreads();

    if (tid == 0) {
        unsigned long long k[8];
#pragma unroll
        for (int j = 0; j < 8; j++) k[j] = 0ull;
        for (int i = 0; i < 64; i++) {
            unsigned long long key = s[i];
            if (key > k[7]) {
                int p = 7;
#pragma unroll
                for (int q = 7; q > 0; q--) {
                    if (key > k[q - 1]) { k[q] = k[q - 1]; p = q - 1; }
                }
                k[p] = key;
            }
        }
#pragma unroll
        for (int j = 0; j < 8; j++) top[j] = k[j];
    }
    __syncthreads();

    if (tid < 8) {
        unsigned pos = ~(unsigned)(top[tid] & 0xFFFFFFFFull);
        int h = pos >> 8, w = pos & 255;
        const int gid = bc * 8 + tid;
        const float* xf = g_xf + (size_t)bc * PLANE;
        float* po = out + gid * 25;
#pragma unroll
        for (int dy = 0; dy < 5; dy++) {
            int yy = h + dy - 2;
#pragma unroll
            for (int dx = 0; dx < 5; dx++) {
                int xx = w + dx - 2;
                float v = 0.f;
                if (yy >= 0 && yy < 256 && xx >= 0 && xx < 256) v = xf[yy * 256 + xx];
                po[dy * 5 + dx] = v;
            }
        }
        float* pp = out + B_ * COUT * NUM_ * 25 + gid * 4;
        pp[0] = (float)min(max(w - 2, 0), 255);
        pp[1] = (float)min(max(h - 2, 0), 255);
        pp[2] = (float)min(max(w + 2, 0), 255);
        pp[3] = (float)min(max(h + 2, 0), 255);
    }
}

// ---------------- launch ------------------------------------------------------
extern "C" void kernel_launch(void* const* d_in, const int* in_sizes, int n_in,
                              void* d_out, int out_size) {
    const float* x      = (const float*)d_in[0];
    const float* w1     = (const float*)d_in[1];
    const float* b1     = (const float*)d_in[2];
    const float* gamma1 = (const float*)d_in[3];
    const float* beta1  = (const float*)d_in[4];
    const float* mean1  = (const float*)d_in[5];
    const float* var1   = (const float*)d_in[6];
    const float* w2     = (const float*)d_in[7];
    const float* gamma2 = (const float*)d_in[8];
    const float* beta2  = (const float*)d_in[9];
    const float* mean2  = (const float*)d_in[10];
    const float* var2   = (const float*)d_in[11];
    float* out = (float*)d_out;

    dim3 cg(2, 64, B_ * 4);
    k_conv1<<<cg, 256>>>(x, w1, b1, gamma1, beta1, mean1, var1);

    k_conv2rs<<<B_ * 256, 256>>>(w2, gamma2, beta2, mean2, var2);
    k_wsmax<<<B_ * COUT * 256, 256>>>();

    k_topk1<<<B_ * COUT * 8, 256>>>();
    k_topk2<<<B_ * COUT, 64>>>(out);
}